// round 1
// baseline (speedup 1.0000x reference)
#include <cuda_runtime.h>

// Problem constants
#define Bn   4
#define Cn   256
#define Hn   128
#define Wn   256
#define CQKn 64
#define COUTn 256
#define HWn  (Hn * Wn)   // 32768

// Scratch for q, k, v projections (device globals: allowed scratch path)
__device__ float g_q[(size_t)Bn * CQKn  * HWn];  // 33.5 MB
__device__ float g_k[(size_t)Bn * CQKn  * HWn];  // 33.5 MB
__device__ float g_v[(size_t)Bn * COUTn * HWn];  // 134 MB

// ---------------------------------------------------------------------------
// Projection GEMM: Y[b, m, p] = sum_c Wm[m, c] * X[b, c, p] + bias[m]
// Block tile: M=64, N=128, K-chunk=32. Threads: 256 (16x16), micro 4(m)x8(n).
// ---------------------------------------------------------------------------
__global__ __launch_bounds__(256) void proj_kernel(
    const float* __restrict__ X, const float* __restrict__ Wm,
    const float* __restrict__ bias, float* __restrict__ Y, int M)
{
    __shared__ float Ws[64 * 33];    // [m][kk], pad 33
    __shared__ float Xs[32 * 132];   // [kk][n], pad 132 (16B aligned rows)

    const int tid = threadIdx.x;
    const int tx = tid & 15;         // n group
    const int ty = tid >> 4;         // m group
    const int n0 = blockIdx.x * 128;
    const int bm = blockIdx.y * 64;
    const int b  = blockIdx.z;

    const float* Xb = X + (size_t)b * Cn * HWn;

    float acc[4][8];
#pragma unroll
    for (int i = 0; i < 4; i++)
#pragma unroll
        for (int j = 0; j < 8; j++) acc[i][j] = 0.f;

    for (int k0 = 0; k0 < Cn; k0 += 32) {
        // Load W tile 64x32 (coalesced 128B rows)
#pragma unroll
        for (int idx = tid; idx < 64 * 32; idx += 256) {
            int m  = idx >> 5;
            int kk = idx & 31;
            Ws[m * 33 + kk] = Wm[(size_t)(bm + m) * Cn + k0 + kk];
        }
        // Load X tile 32x128 (coalesced)
#pragma unroll
        for (int idx = tid; idx < 32 * 128; idx += 256) {
            int kk = idx >> 7;
            int n  = idx & 127;
            Xs[kk * 132 + n] = Xb[(size_t)(k0 + kk) * HWn + n0 + n];
        }
        __syncthreads();

#pragma unroll
        for (int kk = 0; kk < 32; kk++) {
            float a0 = Ws[(ty * 4 + 0) * 33 + kk];
            float a1 = Ws[(ty * 4 + 1) * 33 + kk];
            float a2 = Ws[(ty * 4 + 2) * 33 + kk];
            float a3 = Ws[(ty * 4 + 3) * 33 + kk];
            float4 x0 = *(const float4*)&Xs[kk * 132 + tx * 8];
            float4 x1 = *(const float4*)&Xs[kk * 132 + tx * 8 + 4];
            float xb[8] = {x0.x, x0.y, x0.z, x0.w, x1.x, x1.y, x1.z, x1.w};
#pragma unroll
            for (int j = 0; j < 8; j++) {
                acc[0][j] += a0 * xb[j];
                acc[1][j] += a1 * xb[j];
                acc[2][j] += a2 * xb[j];
                acc[3][j] += a3 * xb[j];
            }
        }
        __syncthreads();
    }

    // Epilogue: add bias, store float4 x2 per m-row
#pragma unroll
    for (int um = 0; um < 4; um++) {
        int m = bm + ty * 4 + um;
        float bb = bias[m];
        size_t base = (size_t)b * M * HWn + (size_t)m * HWn + n0 + tx * 8;
        float4 o0 = {acc[um][0] + bb, acc[um][1] + bb, acc[um][2] + bb, acc[um][3] + bb};
        float4 o1 = {acc[um][4] + bb, acc[um][5] + bb, acc[um][6] + bb, acc[um][7] + bb};
        *(float4*)&Y[base]     = o0;
        *(float4*)&Y[base + 4] = o1;
    }
}

// ---------------------------------------------------------------------------
// Width-axial attention. One block per (query-tile qt, h, b).
//   energy[i, j] = sum_d q[d, wq0+i] * k[d, j]      (i<64 queries, j<256 keys)
//   att = softmax_j(energy)  (normalization deferred to epilogue)
//   out[o, wq0+i] = (sum_j v[o, j] * exp(e[i,j]-max_i)) * (1/sum_i)
// Shared layout (floats):
//   q_s  [d][i]     64*64    @ 0
//   k_s  [d][j]     64*256   @ 4096
//   a_s  [j][i]     256*68   @ 20480   (transposed energy/att, pad 68)
//   v_s  [o][jj]    256*33   @ 37888   (32-key chunk of v, pad 33)
//   red             576      @ 46336   (max[256] | sum[256] | rinv[64])
// Total 46912 floats = 187648 B dynamic smem.
// ---------------------------------------------------------------------------
__global__ __launch_bounds__(256) void attn_kernel(float* __restrict__ out)
{
    extern __shared__ float sm[];
    float* q_s = sm;
    float* k_s = sm + 4096;
    float* a_s = sm + 20480;
    float* v_s = sm + 37888;
    float* red = sm + 46336;

    const int tid = threadIdx.x;
    const int tx = tid & 15;
    const int ty = tid >> 4;
    const int qt = blockIdx.x;     // query tile (0..3)
    const int h  = blockIdx.y;
    const int b  = blockIdx.z;
    const int wq0 = qt * 64;

    const size_t rowqk = (size_t)b * CQKn * HWn + (size_t)h * Wn;

    // Load q tile [64 d][64 i]
#pragma unroll
    for (int idx = tid; idx < 64 * 64; idx += 256) {
        int d = idx >> 6, i = idx & 63;
        q_s[idx] = g_q[rowqk + (size_t)d * HWn + wq0 + i];
    }
    // Load k slice [64 d][256 j]
#pragma unroll
    for (int idx = tid; idx < 64 * 256; idx += 256) {
        int d = idx >> 8, j = idx & 255;
        k_s[idx] = g_k[rowqk + (size_t)d * HWn + j];
    }
    __syncthreads();

    // --- Energy GEMM: e[m][u] = att[j = ty+16m][i = tx*4+u] ---
    float e[16][4];
#pragma unroll
    for (int m = 0; m < 16; m++)
#pragma unroll
        for (int u = 0; u < 4; u++) e[m][u] = 0.f;

    for (int d = 0; d < 64; d++) {
        float4 qa = *(const float4*)&q_s[d * 64 + tx * 4];
#pragma unroll
        for (int m = 0; m < 16; m++) {
            float kb = k_s[d * 256 + ty + 16 * m];
            e[m][0] += kb * qa.x;
            e[m][1] += kb * qa.y;
            e[m][2] += kb * qa.z;
            e[m][3] += kb * qa.w;
        }
    }
#pragma unroll
    for (int m = 0; m < 16; m++) {
        float4 st = {e[m][0], e[m][1], e[m][2], e[m][3]};
        *(float4*)&a_s[(ty + 16 * m) * 68 + tx * 4] = st;
    }
    __syncthreads();

    // --- Softmax over j per query i (4 threads per i) ---
    {
        const int i  = tid & 63;
        const int qr = tid >> 6;           // j quarter
        float lm = -1e30f;
#pragma unroll 8
        for (int jj = 0; jj < 64; jj++)
            lm = fmaxf(lm, a_s[(qr * 64 + jj) * 68 + i]);
        red[qr * 64 + i] = lm;
        __syncthreads();
        float rm = fmaxf(fmaxf(red[i], red[64 + i]), fmaxf(red[128 + i], red[192 + i]));
        float ls = 0.f;
#pragma unroll 8
        for (int jj = 0; jj < 64; jj++) {
            float ex = __expf(a_s[(qr * 64 + jj) * 68 + i] - rm);
            a_s[(qr * 64 + jj) * 68 + i] = ex;
            ls += ex;
        }
        red[256 + qr * 64 + i] = ls;
        __syncthreads();
        if (tid < 64) {
            float s = red[256 + tid] + red[320 + tid] + red[384 + tid] + red[448 + tid];
            red[512 + tid] = 1.0f / s;
        }
        // visibility of red[512..] + a_s covered by first sync in AV loop
    }

    // --- AV GEMM: out[o = ty+16r][i = tx*4+u], stream v in 32-key chunks ---
    float acc2[16][4];
#pragma unroll
    for (int r = 0; r < 16; r++)
#pragma unroll
        for (int u = 0; u < 4; u++) acc2[r][u] = 0.f;

    const size_t vbase = (size_t)b * COUTn * HWn + (size_t)h * Wn;

    for (int jc = 0; jc < 8; jc++) {
        const int jbase = jc * 32;
        __syncthreads();   // protect v_s reuse (and rinv/a_s on first iter)
#pragma unroll
        for (int idx = tid; idx < 256 * 32; idx += 256) {
            int o = idx >> 5, jj = idx & 31;
            v_s[o * 33 + jj] = g_v[vbase + (size_t)o * HWn + jbase + jj];
        }
        __syncthreads();

#pragma unroll 4
        for (int jj = 0; jj < 32; jj++) {
            float4 aa = *(const float4*)&a_s[(jbase + jj) * 68 + tx * 4];
#pragma unroll
            for (int r = 0; r < 16; r++) {
                float vv = v_s[(ty + 16 * r) * 33 + jj];
                acc2[r][0] += vv * aa.x;
                acc2[r][1] += vv * aa.y;
                acc2[r][2] += vv * aa.z;
                acc2[r][3] += vv * aa.w;
            }
        }
    }

    // Epilogue: apply deferred 1/sum, store float4 (fully coalesced)
    float rv0 = red[512 + tx * 4 + 0];
    float rv1 = red[512 + tx * 4 + 1];
    float rv2 = red[512 + tx * 4 + 2];
    float rv3 = red[512 + tx * 4 + 3];
    size_t obase = (size_t)b * COUTn * HWn + (size_t)h * Wn + wq0 + tx * 4;
#pragma unroll
    for (int r = 0; r < 16; r++) {
        int o = ty + 16 * r;
        float4 ov = {acc2[r][0] * rv0, acc2[r][1] * rv1, acc2[r][2] * rv2, acc2[r][3] * rv3};
        *(float4*)&out[obase + (size_t)o * HWn] = ov;
    }
}

// ---------------------------------------------------------------------------
extern "C" void kernel_launch(void* const* d_in, const int* in_sizes, int n_in,
                              void* d_out, int out_size)
{
    const float* flow   = (const float*)d_in[0];
    const float* de_out = (const float*)d_in[1];
    const float* Wq     = (const float*)d_in[2];
    const float* bq     = (const float*)d_in[3];
    const float* Wk     = (const float*)d_in[4];
    const float* bk     = (const float*)d_in[5];
    const float* Wv     = (const float*)d_in[6];
    const float* bv     = (const float*)d_in[7];
    float* out = (float*)d_out;

    float *qp, *kp, *vp;
    cudaGetSymbolAddress((void**)&qp, g_q);
    cudaGetSymbolAddress((void**)&kp, g_k);
    cudaGetSymbolAddress((void**)&vp, g_v);

    const int ATT_SMEM = 46912 * 4;  // 187648 B
    cudaFuncSetAttribute(attn_kernel, cudaFuncAttributeMaxDynamicSharedMemorySize, ATT_SMEM);

    dim3 blk(256);
    // q = Wq * de_out + bq
    proj_kernel<<<dim3(HWn / 128, CQKn / 64, Bn), blk>>>(de_out, Wq, bq, qp, CQKn);
    // k = Wk * flow + bk
    proj_kernel<<<dim3(HWn / 128, CQKn / 64, Bn), blk>>>(flow, Wk, bk, kp, CQKn);
    // v = Wv * flow + bv
    proj_kernel<<<dim3(HWn / 128, COUTn / 64, Bn), blk>>>(flow, Wv, bv, vp, COUTn);
    // attention
    attn_kernel<<<dim3(Wn / 64, Hn, Bn), blk, ATT_SMEM>>>(out);
}